// round 13
// baseline (speedup 1.0000x reference)
#include <cuda_runtime.h>
#include <cuda_fp16.h>
#include <cstdint>

#define NN   2048
#define FIN  16
#define TT   12
#define FOUT 32
#define BB   8
#define FT   192
#define WSTR 40      // k_main padded row stride in halves (80 B)
#define S2STR 72     // k_s2 padded row stride in halves (144 B), KC=64

typedef unsigned int u32;

// ------------------------------ scratch globals ------------------------------
__device__ float g_S  [NN*(size_t)NN];
__device__ float g_ST [NN*(size_t)NN];
__device__ float g_S2T[NN*(size_t)NN];
__device__ __half g_Shi [NN*(size_t)NN];   // S * 1024 fp16
__device__ __half g_SThi[NN*(size_t)NN];   // ST * 1024 fp16
__device__ __half g_xThi[BB*(size_t)FT*NN];// x^T fp16

// ------------------------------ helpers ------------------------------
__device__ __forceinline__ u32 smem_u32(const void* p) {
    u32 a;
    asm("{ .reg .u64 t; cvta.to.shared.u64 t, %1; cvt.u32.u64 %0, t; }" : "=r"(a) : "l"(p));
    return a;
}
__device__ __forceinline__ void cp16(u32 dst, const void* src) {
    asm volatile("cp.async.cg.shared.global [%0], [%1], 16;" :: "r"(dst), "l"(src));
}
#define CP_COMMIT() asm volatile("cp.async.commit_group;" ::: "memory")
#define CP_WAIT(n)  asm volatile("cp.async.wait_group %0;" :: "n"(n) : "memory")

__device__ __forceinline__ void ldsm_x4(u32* r, u32 addr) {
    asm volatile("ldmatrix.sync.aligned.m8n8.x4.shared.b16 {%0,%1,%2,%3}, [%4];"
        : "=r"(r[0]), "=r"(r[1]), "=r"(r[2]), "=r"(r[3]) : "r"(addr));
}
__device__ __forceinline__ void ldsm_x2(u32* r, u32 addr) {
    asm volatile("ldmatrix.sync.aligned.m8n8.x2.shared.b16 {%0,%1}, [%2];"
        : "=r"(r[0]), "=r"(r[1]) : "r"(addr));
}
__device__ __forceinline__ void mma_f16(float* d, const u32* a, const u32* b) {
    asm volatile("mma.sync.aligned.m16n8k16.row.col.f32.f16.f16.f32 "
        "{%0,%1,%2,%3}, {%4,%5,%6,%7}, {%8,%9}, {%0,%1,%2,%3};"
        : "+f"(d[0]), "+f"(d[1]), "+f"(d[2]), "+f"(d[3])
        : "r"(a[0]), "r"(a[1]), "r"(a[2]), "r"(a[3]), "r"(b[0]), "r"(b[1]));
}

// ---------------------------------------------------------------------------
// Kernel 1: S = softmax(relu(E E^T), axis=1); 8 rows per block
// ---------------------------------------------------------------------------
__global__ __launch_bounds__(256)
void k_supports(const float* __restrict__ E) {
    extern __shared__ float sms[];
    float* rows = sms;              // 8*2048
    float* e8   = sms + 8*NN;       // 128
    float* pr   = e8 + 128;         // 8*256
    __shared__ float bc[8];

    const int i0  = blockIdx.x * 8;
    const int tid = threadIdx.x;
    const int w   = tid >> 5, lane = tid & 31;

    if (tid < 128) e8[tid] = E[(i0 + (tid >> 4))*FIN + (tid & 15)];
    __syncthreads();

    float lv[8];
    #pragma unroll
    for (int r = 0; r < 8; r++) lv[r] = 0.f;

    for (int j = tid; j < NN; j += 256) {
        float ej[16];
        const float4* p4 = reinterpret_cast<const float4*>(E + (size_t)j*FIN);
        #pragma unroll
        for (int q = 0; q < 4; q++) {
            float4 v = p4[q];
            ej[q*4+0] = v.x; ej[q*4+1] = v.y; ej[q*4+2] = v.z; ej[q*4+3] = v.w;
        }
        #pragma unroll
        for (int r = 0; r < 8; r++) {
            float dot = 0.f;
            #pragma unroll
            for (int q = 0; q < 16; q++) dot = fmaf(ej[q], e8[r*16+q], dot);
            float rv = fmaxf(dot, 0.f);
            rows[r*NN + j] = rv;
            lv[r] = fmaxf(lv[r], rv);
        }
    }
    #pragma unroll
    for (int r = 0; r < 8; r++) pr[r*256 + tid] = lv[r];
    __syncthreads();
    {
        float m = pr[w*256 + lane];
        #pragma unroll
        for (int o = 1; o < 8; o++) m = fmaxf(m, pr[w*256 + o*32 + lane]);
        #pragma unroll
        for (int o = 16; o > 0; o >>= 1) m = fmaxf(m, __shfl_xor_sync(0xffffffffu, m, o));
        if (lane == 0) bc[w] = m;
    }
    __syncthreads();
    float bmax[8];
    #pragma unroll
    for (int r = 0; r < 8; r++) { bmax[r] = bc[r]; lv[r] = 0.f; }
    __syncthreads();

    for (int j = tid; j < NN; j += 256)
        #pragma unroll
        for (int r = 0; r < 8; r++) {
            float e = expf(rows[r*NN + j] - bmax[r]);
            rows[r*NN + j] = e;
            lv[r] += e;
        }
    #pragma unroll
    for (int r = 0; r < 8; r++) pr[r*256 + tid] = lv[r];
    __syncthreads();
    {
        float s = pr[w*256 + lane];
        #pragma unroll
        for (int o = 1; o < 8; o++) s += pr[w*256 + o*32 + lane];
        #pragma unroll
        for (int o = 16; o > 0; o >>= 1) s += __shfl_xor_sync(0xffffffffu, s, o);
        if (lane == 0) bc[w] = 1.0f / s;
    }
    __syncthreads();
    float inv[8];
    #pragma unroll
    for (int r = 0; r < 8; r++) inv[r] = bc[r];

    for (int j = tid; j < NN; j += 256)
        #pragma unroll
        for (int r = 0; r < 8; r++) {
            float v = rows[r*NN + j] * inv[r];
            size_t o = (size_t)(i0 + r)*NN + j;
            g_S[o]   = v;
            g_Shi[o] = __float2half_rn(v * 1024.f);
        }
}

// ---------------------------------------------------------------------------
// Kernel 2: ST (fp32) + SThi (fp16 of ST*1024)
// ---------------------------------------------------------------------------
__global__ __launch_bounds__(256)
void k_prepS() {
    __shared__ float t[64][65];
    const int tid = threadIdx.x;
    const int i0 = blockIdx.y*64, j0 = blockIdx.x*64;

    for (int idx = tid; idx < 1024; idx += 256) {
        int r = idx >> 4, q = idx & 15;
        float4 v = *reinterpret_cast<const float4*>(&g_S[(size_t)(i0+r)*NN + j0 + q*4]);
        t[r][q*4+0] = v.x; t[r][q*4+1] = v.y; t[r][q*4+2] = v.z; t[r][q*4+3] = v.w;
    }
    __syncthreads();
    for (int idx = tid; idx < 4096; idx += 256) {
        int c = idx >> 6, r = idx & 63;
        float v = t[r][c];
        size_t o = (size_t)(j0+c)*NN + i0 + r;
        g_ST[o] = v;
        g_SThi[o] = __float2half_rn(v * 1024.f);
    }
}

// ---------------------------------------------------------------------------
// Kernel 3: xT[b][ft][n] fp16
// ---------------------------------------------------------------------------
__global__ __launch_bounds__(256)
void k_prepx(const float* __restrict__ x) {
    __shared__ float t[FT][33];
    const int tid = threadIdx.x;
    const int b  = blockIdx.y;
    const int n0 = blockIdx.x*32;
    const float* xb = x + (size_t)b*NN*FT;

    for (int idx = tid; idx < 32*48; idx += 256) {
        int r = idx / 48, q = idx % 48;
        float4 v = *reinterpret_cast<const float4*>(&xb[(size_t)(n0+r)*FT + q*4]);
        t[q*4+0][r] = v.x; t[q*4+1][r] = v.y; t[q*4+2][r] = v.z; t[q*4+3][r] = v.w;
    }
    __syncthreads();
    for (int idx = tid; idx < FT*32; idx += 256) {
        int ft = idx >> 5, n = idx & 31;
        size_t o = ((size_t)b*FT + ft)*NN + n0 + n;
        g_xThi[o] = __float2half_rn(t[ft][n]);
    }
}

// ---------------------------------------------------------------------------
// Kernel 4: S2T[i][j] = sum_k ST[i,k]*S[j,k]  (fp16 single-pass, scaled 2^20)
// CTA 128(i) x 256(j), 256 thr, 8 warps (2x4), warp tile 64x64, KC=64.
// ---------------------------------------------------------------------------
#define S2_BUFH (384*S2STR)     // halves per buffer
#define S2_BH   (128*S2STR)

__global__ __launch_bounds__(256, 1)
void k_s2() {
    extern __shared__ __align__(16) __half sh[];
    const int tid = threadIdx.x, w = tid >> 5, lane = tid & 31;
    const int wm = w >> 2, wn = w & 3;
    const int i0 = blockIdx.y*128, j0 = blockIdx.x*256;
    const u32 sb = smem_u32(sh);

    float d[4][8][4];
    #pragma unroll
    for (int mt = 0; mt < 4; mt++)
        #pragma unroll
        for (int nt = 0; nt < 8; nt++)
            #pragma unroll
            for (int e = 0; e < 4; e++) d[mt][nt][e] = 0.f;

    auto stage = [&](int ch) {
        const int n0 = ch*64;
        const u32 bufb = sb + (u32)((ch & 1) * S2_BUFH * 2);
        #pragma unroll
        for (int idx = tid; idx < 3072; idx += 256) {
            int ru = idx >> 3, q = idx & 7;
            const __half* src;
            int grow, dbase;
            if (ru < 128) { src = g_SThi; grow = i0 + ru;       dbase = 0; }
            else          { src = g_Shi;  grow = j0 + ru - 128; dbase = S2_BH; ru -= 128; }
            u32 dst = bufb + (u32)((dbase + ru*S2STR + q*8)*2);
            cp16(dst, src + (size_t)grow*NN + n0 + q*8);
        }
    };

    stage(0); CP_COMMIT();

    for (int ch = 0; ch < 32; ch++) {
        if (ch < 31) { stage(ch+1); CP_COMMIT(); CP_WAIT(1); }
        else         { CP_WAIT(0); }
        __syncthreads();

        const u32 bufb = sb + (u32)((ch & 1) * S2_BUFH * 2);
        #pragma unroll
        for (int ks = 0; ks < 4; ks++) {
            u32 ah[4][4], bh[8][2];
            const int arow = wm*64 + (lane & 15);
            const int acol = ks*16 + (lane >> 4)*8;
            const int brow = wn*64 + (lane & 7);
            const int bcol = ks*16 + ((lane >> 3) & 1)*8;
            #pragma unroll
            for (int nt = 0; nt < 8; nt++)
                ldsm_x2(bh[nt], bufb + (u32)(((S2_BH + (brow + nt*8)*S2STR) + bcol)*2));
            #pragma unroll
            for (int mt = 0; mt < 4; mt++)
                ldsm_x4(ah[mt], bufb + (u32)((((arow + mt*16)*S2STR) + acol)*2));
            #pragma unroll
            for (int mt = 0; mt < 4; mt++)
                #pragma unroll
                for (int nt = 0; nt < 8; nt++)
                    mma_f16(d[mt][nt], ah[mt], bh[nt]);
        }
        __syncthreads();
    }
    const float sc = 1.f / (1024.f*1024.f);
    #pragma unroll
    for (int mt = 0; mt < 4; mt++)
        #pragma unroll
        for (int nt = 0; nt < 8; nt++) {
            int row = i0 + wm*64 + mt*16 + (lane >> 2);
            int col = j0 + wn*64 + nt*8 + (lane & 3)*2;
            *reinterpret_cast<float2*>(&g_S2T[(size_t)row*NN + col]) =
                make_float2(d[mt][nt][0]*sc, d[mt][nt][1]*sc);
            *reinterpret_cast<float2*>(&g_S2T[(size_t)(row+8)*NN + col]) =
                make_float2(d[mt][nt][2]*sc, d[mt][nt][3]*sc);
        }
}

// ---------------------------------------------------------------------------
// Kernel 5: masked dual-GEMM + FUSED theta epilogue + relu
//   W rows 0-63 : W1 = ST*A*1024 ; rows 64-127: W2 = S2T*A*2048
//   out[m,o,t] = relu(sum_f r1*th1 + r2*th2 + A[m,m]*x[m,ft]*(th0-th2))
// CTA: 256 thr, 2 CTAs/SM, M=128, N=192, KC=32, 8 warps (2x4), warp tile 64x48
// ---------------------------------------------------------------------------
#define KM_W(p)    ((p)*5120)                // halves: 128*40
#define KM_X(p)    (10240 + (p)*7680)        // halves: 192*40
#define KM_RAWB    51200                     // bytes
#define KM_STB     (KM_RAWB)
#define KM_S2B     (KM_RAWB + 8192)
#define KM_AB      (KM_RAWB + 16384)
#define KM_SMEM    (KM_RAWB + 25088)         // 76288 B -> 2 CTAs/SM

__global__ __launch_bounds__(256, 2)
void k_main(const float* __restrict__ A, const float* __restrict__ x,
            const float* __restrict__ theta, float* __restrict__ out) {
    extern __shared__ __align__(16) __half sh[];
    char* shc = reinterpret_cast<char*>(sh);
    const int tid = threadIdx.x, w = tid >> 5, lane = tid & 31;
    const int wm = w >> 2, wn = w & 3;
    const int m0 = blockIdx.x*64;
    const int b  = blockIdx.y;
    const u32 sb = smem_u32(sh);

    const float* Ab = A + (size_t)b*NN*NN;
    const float* xb = x + (size_t)b*NN*FT;
    const __half* xh = g_xThi + (size_t)b*FT*NN;
    float* stST = reinterpret_cast<float*>(shc + KM_STB);
    float* stS2 = reinterpret_cast<float*>(shc + KM_S2B);
    float* As   = reinterpret_cast<float*>(shc + KM_AB);

    float d[4][6][4];
    #pragma unroll
    for (int mt = 0; mt < 4; mt++)
        #pragma unroll
        for (int nt = 0; nt < 6; nt++)
            #pragma unroll
            for (int e = 0; e < 4; e++) d[mt][nt][e] = 0.f;

    auto stage = [&](int ch) {
        const int n0 = ch*32;
        const int p = ch & 1;
        #pragma unroll
        for (int idx = tid; idx < 2304; idx += 256) {
            if (idx < 768) {                 // X: 192 rows x 32 halves
                int row = idx >> 2, q = idx & 3;
                u32 dst = sb + (u32)((KM_X(p) + row*WSTR + q*8)*2);
                cp16(dst, xh + (size_t)row*NN + n0 + q*8);
            } else if (idx < 1792) {         // raw ST/S2T: 2 x 64 rows x 32 f32
                int j = idx - 768;
                int sel = j >> 9;
                int i = j & 511;
                int row = i >> 3, q = i & 7;
                const float* src = sel ? g_S2T : g_ST;
                u32 dst = sb + (u32)((sel ? KM_S2B : KM_STB) + (row*32 + q*4)*4);
                cp16(dst, src + (size_t)(m0+row)*NN + n0 + q*4);
            } else {                         // raw A: 32 rows x 64 f32 (stride 68)
                int j = idx - 1792;
                int row = j >> 4, q = j & 15;
                u32 dst = sb + (u32)(KM_AB + (row*68 + q*4)*4);
                cp16(dst, Ab + (size_t)(n0+row)*NN + m0 + q*4);
            }
        }
    };

    auto build = [&](int ch) {
        const int p = ch & 1;
        #pragma unroll
        for (int idx = tid; idx < 1024; idx += 256) {
            int m = idx >> 4, pp = idx & 15, n = 2*pp;
            float2 st = *reinterpret_cast<const float2*>(&stST[m*32 + n]);
            float2 s2 = *reinterpret_cast<const float2*>(&stS2[m*32 + n]);
            float a0 = As[n*68 + m], a1 = As[(n+1)*68 + m];
            __half h1x = __float2half_rn(st.x*a0*1024.f);
            __half h1y = __float2half_rn(st.y*a1*1024.f);
            __half h2x = __float2half_rn(s2.x*a0*2048.f);
            __half h2y = __float2half_rn(s2.y*a1*2048.f);
            int base = KM_W(p);
            *reinterpret_cast<__half2*>(shc + (base + m*WSTR + n)*2)      = __halves2half2(h1x, h1y);
            *reinterpret_cast<__half2*>(shc + (base + (64+m)*WSTR + n)*2) = __halves2half2(h2x, h2y);
        }
    };

    auto domma = [&](int ch) {
        const int p = ch & 1;
        const u32 wbase = sb + (u32)(KM_W(p)*2);
        const u32 xbase = sb + (u32)(KM_X(p)*2);
        #pragma unroll
        for (int ks = 0; ks < 2; ks++) {
            u32 ah[4][4], bh[6][2];
            const int arow = wm*64 + (lane & 15);
            const int acol = ks*16 + (lane >> 4)*8;
            const int brow = wn*48 + (lane & 7);
            const int bcol = ks*16 + ((lane >> 3) & 1)*8;
            #pragma unroll
            for (int nt = 0; nt < 6; nt++)
                ldsm_x2(bh[nt], xbase + (u32)(((brow + nt*8)*WSTR + bcol)*2));
            #pragma unroll
            for (int mt = 0; mt < 4; mt++)
                ldsm_x4(ah[mt], wbase + (u32)(((arow + mt*16)*WSTR + acol)*2));
            #pragma unroll
            for (int mt = 0; mt < 4; mt++)
                #pragma unroll
                for (int nt = 0; nt < 6; nt++)
                    mma_f16(d[mt][nt], ah[mt], bh[nt]);
        }
    };

    stage(0); CP_COMMIT();
    CP_WAIT(0); __syncthreads();
    build(0); __syncthreads();

    for (int c = 0; c < 64; c++) {
        if (c < 63) { stage(c+1); CP_COMMIT(); }
        domma(c);
        if (c < 63) {
            CP_WAIT(0); __syncthreads();
            build(c+1);
            __syncthreads();
        }
    }

    // ---------------- fused theta epilogue ----------------
    __syncthreads();   // all mma reads of pipeline smem done

    float* ep  = reinterpret_cast<float*>(shc);
    float* er1 = ep;            // 16*192 = 3072
    float* er2 = ep + 3072;     // 3072
    float* es0 = ep + 6144;     // 3072
    float* th1 = ep + 9216;     // 512
    float* th2 = ep + 9728;     // 512
    float* th0 = ep + 10240;    // 512  (theta0 - theta2)
    // theta region (bytes 36864..43008) may overlap pipeline X buffers,
    // but the sync above ordered all reads before these writes.
    for (int i = tid; i < FIN*FOUT; i += 256) {
        th1[i] = theta[512 + i];
        float t2 = theta[1024 + i];
        th2[i]  = t2;
        th0[i]  = theta[i] - t2;
    }

    const float sc = 1.f / 1024.f;
    float* outb = out + (size_t)b*NN*FOUT*TT;

    for (int mt = 0; mt < 4; mt++) {
        __syncthreads();   // previous quarter's reads done / theta visible
        // stage accumulator quarter: wm=0 -> r1, wm=1 -> r2 (16 m rows x 192 ft)
        {
            float* dst = (wm == 0) ? er1 : er2;
            int r16 = lane >> 2;
            int colb = wn*48 + (lane & 3)*2;
            #pragma unroll
            for (int nt = 0; nt < 6; nt++) {
                int col = colb + nt*8;
                dst[r16*FT + col]       = d[mt][nt][0]*sc;
                dst[r16*FT + col + 1]   = d[mt][nt][1]*sc;
                dst[(r16+8)*FT + col]   = d[mt][nt][2]*sc;
                dst[(r16+8)*FT + col+1] = d[mt][nt][3]*sc;
            }
        }
        // stage diagonal term s0[r][ft] = A[mg,mg] * x[mg,ft]
        for (int i = tid; i < 16*FT; i += 256) {
            int r = i / FT, c = i - r*FT;
            int mg = m0 + mt*16 + r;
            float dg = Ab[(size_t)mg*NN + mg];
            es0[i] = dg * xb[(size_t)mg*FT + c];
        }
        __syncthreads();
        // contract with theta + relu, write out
        for (int idx = tid; idx < 16*FOUT*TT; idx += 256) {
            int m = idx / (FOUT*TT);
            int r = idx - m*(FOUT*TT);
            int o = r / TT, t = r - o*TT;
            float val = 0.f;
            #pragma unroll
            for (int f = 0; f < FIN; f++) {
                int ft = f*TT + t;
                val = fmaf(er1[m*FT + ft], th1[f*FOUT + o], val);
                val = fmaf(er2[m*FT + ft], th2[f*FOUT + o], val);
                val = fmaf(es0[m*FT + ft], th0[f*FOUT + o], val);
            }
            outb[(size_t)(m0 + mt*16 + m)*FOUT*TT + r] = fmaxf(val, 0.f);
        }
    }
}

// ---------------------------------------------------------------------------
extern "C" void kernel_launch(void* const* d_in, const int* in_sizes, int n_in,
                              void* d_out, int out_size) {
    const float *x = nullptr, *A = nullptr, *E = nullptr, *theta = nullptr;
    for (int i = 0; i < n_in; i++) {
        switch (in_sizes[i]) {
            case BB*NN*FIN*TT:   x     = (const float*)d_in[i]; break;
            case BB*NN*NN:       A     = (const float*)d_in[i]; break;
            case NN*FIN:         E     = (const float*)d_in[i]; break;
            case 3*FIN*FOUT:     theta = (const float*)d_in[i]; break;
        }
    }
    float* out = (float*)d_out;

    const int sup_smem = (8*NN + 128 + 8*256) * (int)sizeof(float);
    cudaFuncSetAttribute(k_supports, cudaFuncAttributeMaxDynamicSharedMemorySize, sup_smem);
    k_supports<<<NN/8, 256, sup_smem>>>(E);

    k_prepS<<<dim3(32, 32), 256>>>();
    k_prepx<<<dim3(64, BB), 256>>>(x);

    const int s2_smem = 2 * S2_BUFH * 2;   // 110592 B
    cudaFuncSetAttribute(k_s2, cudaFuncAttributeMaxDynamicSharedMemorySize, s2_smem);
    k_s2<<<dim3(8, 16), 256, s2_smem>>>();

    cudaFuncSetAttribute(k_main, cudaFuncAttributeMaxDynamicSharedMemorySize, KM_SMEM);
    k_main<<<dim3(32, BB), 256, KM_SMEM>>>(A, x, theta, out);
}

// round 14
// speedup vs baseline: 2.4696x; 2.4696x over previous
#include <cuda_runtime.h>
#include <cuda_fp16.h>
#include <cstdint>

#define NN   2048
#define FIN  16
#define TT   12
#define FOUT 32
#define BB   8
#define FT   192
#define WSTR 40      // k_main padded row stride in halves (80 B)
#define S2STR 72     // k_s2 padded row stride in halves (144 B), KC=64

typedef unsigned int u32;

// ------------------------------ scratch globals ------------------------------
__device__ float g_S  [NN*(size_t)NN];
__device__ float g_ST [NN*(size_t)NN];
__device__ float g_S2T[NN*(size_t)NN];
__device__ __half g_Shi [NN*(size_t)NN];   // S * 1024 fp16
__device__ __half g_SThi[NN*(size_t)NN];   // ST * 1024 fp16
__device__ __half g_xThi[BB*(size_t)FT*NN];// x^T fp16

// ------------------------------ helpers ------------------------------
__device__ __forceinline__ u32 smem_u32(const void* p) {
    u32 a;
    asm("{ .reg .u64 t; cvta.to.shared.u64 t, %1; cvt.u32.u64 %0, t; }" : "=r"(a) : "l"(p));
    return a;
}
__device__ __forceinline__ void cp16(u32 dst, const void* src) {
    asm volatile("cp.async.cg.shared.global [%0], [%1], 16;" :: "r"(dst), "l"(src));
}
#define CP_COMMIT() asm volatile("cp.async.commit_group;" ::: "memory")
#define CP_WAIT(n)  asm volatile("cp.async.wait_group %0;" :: "n"(n) : "memory")

__device__ __forceinline__ void ldsm_x4(u32* r, u32 addr) {
    asm volatile("ldmatrix.sync.aligned.m8n8.x4.shared.b16 {%0,%1,%2,%3}, [%4];"
        : "=r"(r[0]), "=r"(r[1]), "=r"(r[2]), "=r"(r[3]) : "r"(addr));
}
__device__ __forceinline__ void ldsm_x2(u32* r, u32 addr) {
    asm volatile("ldmatrix.sync.aligned.m8n8.x2.shared.b16 {%0,%1}, [%2];"
        : "=r"(r[0]), "=r"(r[1]) : "r"(addr));
}
__device__ __forceinline__ void mma_f16(float* d, const u32* a, const u32* b) {
    asm volatile("mma.sync.aligned.m16n8k16.row.col.f32.f16.f16.f32 "
        "{%0,%1,%2,%3}, {%4,%5,%6,%7}, {%8,%9}, {%0,%1,%2,%3};"
        : "+f"(d[0]), "+f"(d[1]), "+f"(d[2]), "+f"(d[3])
        : "r"(a[0]), "r"(a[1]), "r"(a[2]), "r"(a[3]), "r"(b[0]), "r"(b[1]));
}

// ---------------------------------------------------------------------------
// Kernel 1: S = softmax(relu(E E^T), axis=1); 8 rows per block
// ---------------------------------------------------------------------------
__global__ __launch_bounds__(256)
void k_supports(const float* __restrict__ E) {
    extern __shared__ float sms[];
    float* rows = sms;              // 8*2048
    float* e8   = sms + 8*NN;       // 128
    float* pr   = e8 + 128;         // 8*256
    __shared__ float bc[8];

    const int i0  = blockIdx.x * 8;
    const int tid = threadIdx.x;
    const int w   = tid >> 5, lane = tid & 31;

    if (tid < 128) e8[tid] = E[(i0 + (tid >> 4))*FIN + (tid & 15)];
    __syncthreads();

    float lv[8];
    #pragma unroll
    for (int r = 0; r < 8; r++) lv[r] = 0.f;

    for (int j = tid; j < NN; j += 256) {
        float ej[16];
        const float4* p4 = reinterpret_cast<const float4*>(E + (size_t)j*FIN);
        #pragma unroll
        for (int q = 0; q < 4; q++) {
            float4 v = p4[q];
            ej[q*4+0] = v.x; ej[q*4+1] = v.y; ej[q*4+2] = v.z; ej[q*4+3] = v.w;
        }
        #pragma unroll
        for (int r = 0; r < 8; r++) {
            float dot = 0.f;
            #pragma unroll
            for (int q = 0; q < 16; q++) dot = fmaf(ej[q], e8[r*16+q], dot);
            float rv = fmaxf(dot, 0.f);
            rows[r*NN + j] = rv;
            lv[r] = fmaxf(lv[r], rv);
        }
    }
    #pragma unroll
    for (int r = 0; r < 8; r++) pr[r*256 + tid] = lv[r];
    __syncthreads();
    {
        float m = pr[w*256 + lane];
        #pragma unroll
        for (int o = 1; o < 8; o++) m = fmaxf(m, pr[w*256 + o*32 + lane]);
        #pragma unroll
        for (int o = 16; o > 0; o >>= 1) m = fmaxf(m, __shfl_xor_sync(0xffffffffu, m, o));
        if (lane == 0) bc[w] = m;
    }
    __syncthreads();
    float bmax[8];
    #pragma unroll
    for (int r = 0; r < 8; r++) { bmax[r] = bc[r]; lv[r] = 0.f; }
    __syncthreads();

    for (int j = tid; j < NN; j += 256)
        #pragma unroll
        for (int r = 0; r < 8; r++) {
            float e = expf(rows[r*NN + j] - bmax[r]);
            rows[r*NN + j] = e;
            lv[r] += e;
        }
    #pragma unroll
    for (int r = 0; r < 8; r++) pr[r*256 + tid] = lv[r];
    __syncthreads();
    {
        float s = pr[w*256 + lane];
        #pragma unroll
        for (int o = 1; o < 8; o++) s += pr[w*256 + o*32 + lane];
        #pragma unroll
        for (int o = 16; o > 0; o >>= 1) s += __shfl_xor_sync(0xffffffffu, s, o);
        if (lane == 0) bc[w] = 1.0f / s;
    }
    __syncthreads();
    float inv[8];
    #pragma unroll
    for (int r = 0; r < 8; r++) inv[r] = bc[r];

    for (int j = tid; j < NN; j += 256)
        #pragma unroll
        for (int r = 0; r < 8; r++) {
            float v = rows[r*NN + j] * inv[r];
            size_t o = (size_t)(i0 + r)*NN + j;
            g_S[o]   = v;
            g_Shi[o] = __float2half_rn(v * 1024.f);
        }
}

// ---------------------------------------------------------------------------
// Kernel 2: ST (fp32) + SThi (fp16 of ST*1024)
// ---------------------------------------------------------------------------
__global__ __launch_bounds__(256)
void k_prepS() {
    __shared__ float t[64][65];
    const int tid = threadIdx.x;
    const int i0 = blockIdx.y*64, j0 = blockIdx.x*64;

    for (int idx = tid; idx < 1024; idx += 256) {
        int r = idx >> 4, q = idx & 15;
        float4 v = *reinterpret_cast<const float4*>(&g_S[(size_t)(i0+r)*NN + j0 + q*4]);
        t[r][q*4+0] = v.x; t[r][q*4+1] = v.y; t[r][q*4+2] = v.z; t[r][q*4+3] = v.w;
    }
    __syncthreads();
    for (int idx = tid; idx < 4096; idx += 256) {
        int c = idx >> 6, r = idx & 63;
        float v = t[r][c];
        size_t o = (size_t)(j0+c)*NN + i0 + r;
        g_ST[o] = v;
        g_SThi[o] = __float2half_rn(v * 1024.f);
    }
}

// ---------------------------------------------------------------------------
// Kernel 3: xT[b][ft][n] fp16
// ---------------------------------------------------------------------------
__global__ __launch_bounds__(256)
void k_prepx(const float* __restrict__ x) {
    __shared__ float t[FT][33];
    const int tid = threadIdx.x;
    const int b  = blockIdx.y;
    const int n0 = blockIdx.x*32;
    const float* xb = x + (size_t)b*NN*FT;

    for (int idx = tid; idx < 32*48; idx += 256) {
        int r = idx / 48, q = idx % 48;
        float4 v = *reinterpret_cast<const float4*>(&xb[(size_t)(n0+r)*FT + q*4]);
        t[q*4+0][r] = v.x; t[q*4+1][r] = v.y; t[q*4+2][r] = v.z; t[q*4+3][r] = v.w;
    }
    __syncthreads();
    for (int idx = tid; idx < FT*32; idx += 256) {
        int ft = idx >> 5, n = idx & 31;
        size_t o = ((size_t)b*FT + ft)*NN + n0 + n;
        g_xThi[o] = __float2half_rn(t[ft][n]);
    }
}

// ---------------------------------------------------------------------------
// Kernel 4: S2T[i][j] = sum_k ST[i,k]*S[j,k]  (fp16 single-pass, scaled 2^20)
// CTA 128(i) x 256(j), 256 thr, 8 warps (2x4), warp tile 64x64, KC=64.
// ---------------------------------------------------------------------------
#define S2_BUFH (384*S2STR)     // halves per buffer
#define S2_BH   (128*S2STR)

__global__ __launch_bounds__(256, 1)
void k_s2() {
    extern __shared__ __align__(16) __half sh[];
    const int tid = threadIdx.x, w = tid >> 5, lane = tid & 31;
    const int wm = w >> 2, wn = w & 3;
    const int i0 = blockIdx.y*128, j0 = blockIdx.x*256;
    const u32 sb = smem_u32(sh);

    float d[4][8][4];
    #pragma unroll
    for (int mt = 0; mt < 4; mt++)
        #pragma unroll
        for (int nt = 0; nt < 8; nt++)
            #pragma unroll
            for (int e = 0; e < 4; e++) d[mt][nt][e] = 0.f;

    auto stage = [&](int ch) {
        const int n0 = ch*64;
        const u32 bufb = sb + (u32)((ch & 1) * S2_BUFH * 2);
        #pragma unroll
        for (int idx = tid; idx < 3072; idx += 256) {
            int ru = idx >> 3, q = idx & 7;
            const __half* src;
            int grow, dbase;
            if (ru < 128) { src = g_SThi; grow = i0 + ru;       dbase = 0; }
            else          { src = g_Shi;  grow = j0 + ru - 128; dbase = S2_BH; ru -= 128; }
            u32 dst = bufb + (u32)((dbase + ru*S2STR + q*8)*2);
            cp16(dst, src + (size_t)grow*NN + n0 + q*8);
        }
    };

    stage(0); CP_COMMIT();

    for (int ch = 0; ch < 32; ch++) {
        if (ch < 31) { stage(ch+1); CP_COMMIT(); CP_WAIT(1); }
        else         { CP_WAIT(0); }
        __syncthreads();

        const u32 bufb = sb + (u32)((ch & 1) * S2_BUFH * 2);
        #pragma unroll
        for (int ks = 0; ks < 4; ks++) {
            u32 ah[4][4], bh[8][2];
            const int arow = wm*64 + (lane & 15);
            const int acol = ks*16 + (lane >> 4)*8;
            const int brow = wn*64 + (lane & 7);
            const int bcol = ks*16 + ((lane >> 3) & 1)*8;
            #pragma unroll
            for (int nt = 0; nt < 8; nt++)
                ldsm_x2(bh[nt], bufb + (u32)(((S2_BH + (brow + nt*8)*S2STR) + bcol)*2));
            #pragma unroll
            for (int mt = 0; mt < 4; mt++)
                ldsm_x4(ah[mt], bufb + (u32)((((arow + mt*16)*S2STR) + acol)*2));
            #pragma unroll
            for (int mt = 0; mt < 4; mt++)
                #pragma unroll
                for (int nt = 0; nt < 8; nt++)
                    mma_f16(d[mt][nt], ah[mt], bh[nt]);
        }
        __syncthreads();
    }
    const float sc = 1.f / (1024.f*1024.f);
    #pragma unroll
    for (int mt = 0; mt < 4; mt++)
        #pragma unroll
        for (int nt = 0; nt < 8; nt++) {
            int row = i0 + wm*64 + mt*16 + (lane >> 2);
            int col = j0 + wn*64 + nt*8 + (lane & 3)*2;
            *reinterpret_cast<float2*>(&g_S2T[(size_t)row*NN + col]) =
                make_float2(d[mt][nt][0]*sc, d[mt][nt][1]*sc);
            *reinterpret_cast<float2*>(&g_S2T[(size_t)(row+8)*NN + col]) =
                make_float2(d[mt][nt][2]*sc, d[mt][nt][3]*sc);
        }
}

// ---------------------------------------------------------------------------
// Kernel 5: masked dual-GEMM + FUSED theta epilogue + relu
//   W rows 0-63 : W1 = ST*A*1024 ; rows 64-127: W2 = S2T*A*2048
//   out[m,o,t] = relu(sum_f r1*th1 + r2*th2 + A[m,m]*x[m,ft]*(th0-th2))
// CTA: 256 thr, 2 CTAs/SM, M=128, N=192, KC=32, 8 warps (2x4), warp tile 64x48
// Epilogue mt loop is FULLY UNROLLED (r13 bug: dynamic d[] indexing demoted
// the accumulators to local memory and poisoned the whole mainloop).
// ---------------------------------------------------------------------------
#define KM_W(p)    ((p)*5120)                // halves: 128*40
#define KM_X(p)    (10240 + (p)*7680)        // halves: 192*40
#define KM_RAWB    51200                     // bytes
#define KM_STB     (KM_RAWB)
#define KM_S2B     (KM_RAWB + 8192)
#define KM_AB      (KM_RAWB + 16384)
#define KM_SMEM    (KM_RAWB + 25088)         // 76288 B -> 2 CTAs/SM

__global__ __launch_bounds__(256, 2)
void k_main(const float* __restrict__ A, const float* __restrict__ x,
            const float* __restrict__ theta, float* __restrict__ out) {
    extern __shared__ __align__(16) __half sh[];
    char* shc = reinterpret_cast<char*>(sh);
    const int tid = threadIdx.x, w = tid >> 5, lane = tid & 31;
    const int wm = w >> 2, wn = w & 3;
    const int m0 = blockIdx.x*64;
    const int b  = blockIdx.y;
    const u32 sb = smem_u32(sh);

    const float* Ab = A + (size_t)b*NN*NN;
    const float* xb = x + (size_t)b*NN*FT;
    const __half* xh = g_xThi + (size_t)b*FT*NN;
    float* stST = reinterpret_cast<float*>(shc + KM_STB);
    float* stS2 = reinterpret_cast<float*>(shc + KM_S2B);
    float* As   = reinterpret_cast<float*>(shc + KM_AB);

    float d[4][6][4];
    #pragma unroll
    for (int mt = 0; mt < 4; mt++)
        #pragma unroll
        for (int nt = 0; nt < 6; nt++)
            #pragma unroll
            for (int e = 0; e < 4; e++) d[mt][nt][e] = 0.f;

    auto stage = [&](int ch) {
        const int n0 = ch*32;
        const int p = ch & 1;
        #pragma unroll
        for (int idx = tid; idx < 2304; idx += 256) {
            if (idx < 768) {                 // X: 192 rows x 32 halves
                int row = idx >> 2, q = idx & 3;
                u32 dst = sb + (u32)((KM_X(p) + row*WSTR + q*8)*2);
                cp16(dst, xh + (size_t)row*NN + n0 + q*8);
            } else if (idx < 1792) {         // raw ST/S2T: 2 x 64 rows x 32 f32
                int j = idx - 768;
                int sel = j >> 9;
                int i = j & 511;
                int row = i >> 3, q = i & 7;
                const float* src = sel ? g_S2T : g_ST;
                u32 dst = sb + (u32)((sel ? KM_S2B : KM_STB) + (row*32 + q*4)*4);
                cp16(dst, src + (size_t)(m0+row)*NN + n0 + q*4);
            } else {                         // raw A: 32 rows x 64 f32 (stride 68)
                int j = idx - 1792;
                int row = j >> 4, q = j & 15;
                u32 dst = sb + (u32)(KM_AB + (row*68 + q*4)*4);
                cp16(dst, Ab + (size_t)(n0+row)*NN + m0 + q*4);
            }
        }
    };

    auto build = [&](int ch) {
        const int p = ch & 1;
        #pragma unroll
        for (int idx = tid; idx < 1024; idx += 256) {
            int m = idx >> 4, pp = idx & 15, n = 2*pp;
            float2 st = *reinterpret_cast<const float2*>(&stST[m*32 + n]);
            float2 s2 = *reinterpret_cast<const float2*>(&stS2[m*32 + n]);
            float a0 = As[n*68 + m], a1 = As[(n+1)*68 + m];
            __half h1x = __float2half_rn(st.x*a0*1024.f);
            __half h1y = __float2half_rn(st.y*a1*1024.f);
            __half h2x = __float2half_rn(s2.x*a0*2048.f);
            __half h2y = __float2half_rn(s2.y*a1*2048.f);
            int base = KM_W(p);
            *reinterpret_cast<__half2*>(shc + (base + m*WSTR + n)*2)      = __halves2half2(h1x, h1y);
            *reinterpret_cast<__half2*>(shc + (base + (64+m)*WSTR + n)*2) = __halves2half2(h2x, h2y);
        }
    };

    auto domma = [&](int ch) {
        const int p = ch & 1;
        const u32 wbase = sb + (u32)(KM_W(p)*2);
        const u32 xbase = sb + (u32)(KM_X(p)*2);
        #pragma unroll
        for (int ks = 0; ks < 2; ks++) {
            u32 ah[4][4], bh[6][2];
            const int arow = wm*64 + (lane & 15);
            const int acol = ks*16 + (lane >> 4)*8;
            const int brow = wn*48 + (lane & 7);
            const int bcol = ks*16 + ((lane >> 3) & 1)*8;
            #pragma unroll
            for (int nt = 0; nt < 6; nt++)
                ldsm_x2(bh[nt], xbase + (u32)(((brow + nt*8)*WSTR + bcol)*2));
            #pragma unroll
            for (int mt = 0; mt < 4; mt++)
                ldsm_x4(ah[mt], wbase + (u32)(((arow + mt*16)*WSTR + acol)*2));
            #pragma unroll
            for (int mt = 0; mt < 4; mt++)
                #pragma unroll
                for (int nt = 0; nt < 6; nt++)
                    mma_f16(d[mt][nt], ah[mt], bh[nt]);
        }
    };

    stage(0); CP_COMMIT();
    CP_WAIT(0); __syncthreads();
    build(0); __syncthreads();

    for (int c = 0; c < 64; c++) {
        if (c < 63) { stage(c+1); CP_COMMIT(); }
        domma(c);
        if (c < 63) {
            CP_WAIT(0); __syncthreads();
            build(c+1);
            __syncthreads();
        }
    }

    // ---------------- fused theta epilogue (fully unrolled mt) ----------------
    __syncthreads();   // all mma reads of pipeline smem done

    float* ep  = reinterpret_cast<float*>(shc);
    float* er1 = ep;            // 16*192 = 3072
    float* er2 = ep + 3072;     // 3072
    float* es0 = ep + 6144;     // 3072
    float* th1 = ep + 9216;     // 512
    float* th2 = ep + 9728;     // 512
    float* th0 = ep + 10240;    // 512  (theta0 - theta2)
    for (int i = tid; i < FIN*FOUT; i += 256) {
        th1[i] = theta[512 + i];
        float t2 = theta[1024 + i];
        th2[i]  = t2;
        th0[i]  = theta[i] - t2;
    }

    const float sc = 1.f / 1024.f;
    float* outb = out + (size_t)b*NN*FOUT*TT;

    #pragma unroll
    for (int mt = 0; mt < 4; mt++) {
        __syncthreads();   // previous quarter's reads done / theta visible
        // stage accumulator quarter: wm=0 -> r1, wm=1 -> r2 (16 m rows x 192 ft)
        {
            float* dst = (wm == 0) ? er1 : er2;
            int r16 = lane >> 2;
            int colb = wn*48 + (lane & 3)*2;
            #pragma unroll
            for (int nt = 0; nt < 6; nt++) {
                int col = colb + nt*8;
                dst[r16*FT + col]       = d[mt][nt][0]*sc;
                dst[r16*FT + col + 1]   = d[mt][nt][1]*sc;
                dst[(r16+8)*FT + col]   = d[mt][nt][2]*sc;
                dst[(r16+8)*FT + col+1] = d[mt][nt][3]*sc;
            }
        }
        // stage diagonal term s0[r][ft] = A[mg,mg] * x[mg,ft]
        for (int i = tid; i < 16*FT; i += 256) {
            int r = i / FT, c = i - r*FT;
            int mg = m0 + mt*16 + r;
            float dg = Ab[(size_t)mg*NN + mg];
            es0[i] = dg * xb[(size_t)mg*FT + c];
        }
        __syncthreads();
        // contract with theta + relu, write out
        for (int idx = tid; idx < 16*FOUT*TT; idx += 256) {
            int m = idx / (FOUT*TT);
            int r = idx - m*(FOUT*TT);
            int o = r / TT, t = r - o*TT;
            float val = 0.f;
            #pragma unroll
            for (int f = 0; f < FIN; f++) {
                int ft = f*TT + t;
                val = fmaf(er1[m*FT + ft], th1[f*FOUT + o], val);
                val = fmaf(er2[m*FT + ft], th2[f*FOUT + o], val);
                val = fmaf(es0[m*FT + ft], th0[f*FOUT + o], val);
            }
            outb[(size_t)(m0 + mt*16 + m)*FOUT*TT + r] = fmaxf(val, 0.f);
        }
    }
}

// ---------------------------------------------------------------------------
extern "C" void kernel_launch(void* const* d_in, const int* in_sizes, int n_in,
                              void* d_out, int out_size) {
    const float *x = nullptr, *A = nullptr, *E = nullptr, *theta = nullptr;
    for (int i = 0; i < n_in; i++) {
        switch (in_sizes[i]) {
            case BB*NN*FIN*TT:   x     = (const float*)d_in[i]; break;
            case BB*NN*NN:       A     = (const float*)d_in[i]; break;
            case NN*FIN:         E     = (const float*)d_in[i]; break;
            case 3*FIN*FOUT:     theta = (const float*)d_in[i]; break;
        }
    }
    float* out = (float*)d_out;

    const int sup_smem = (8*NN + 128 + 8*256) * (int)sizeof(float);
    cudaFuncSetAttribute(k_supports, cudaFuncAttributeMaxDynamicSharedMemorySize, sup_smem);
    k_supports<<<NN/8, 256, sup_smem>>>(E);

    k_prepS<<<dim3(32, 32), 256>>>();
    k_prepx<<<dim3(64, BB), 256>>>(x);

    const int s2_smem = 2 * S2_BUFH * 2;   // 110592 B
    cudaFuncSetAttribute(k_s2, cudaFuncAttributeMaxDynamicSharedMemorySize, s2_smem);
    k_s2<<<dim3(8, 16), 256, s2_smem>>>();

    cudaFuncSetAttribute(k_main, cudaFuncAttributeMaxDynamicSharedMemorySize, KM_SMEM);
    k_main<<<dim3(32, BB), 256, KM_SMEM>>>(A, x, theta, out);
}

// round 15
// speedup vs baseline: 2.5065x; 1.0149x over previous
#include <cuda_runtime.h>
#include <cuda_fp16.h>
#include <cstdint>

#define NN   2048
#define FIN  16
#define TT   12
#define FOUT 32
#define BB   8
#define FT   192
#define WSTR 40      // k_main padded row stride in halves (80 B)
#define S2STR 72     // k_s2 padded row stride in halves (144 B), KC=64

typedef unsigned int u32;

// ------------------------------ scratch globals ------------------------------
__device__ float g_S  [NN*(size_t)NN];
__device__ __half g_Shi [NN*(size_t)NN];   // S * 1024 fp16
__device__ __half g_SThi[NN*(size_t)NN];   // ST * 1024 fp16
__device__ __half g_S2Th[NN*(size_t)NN];   // S2T * 2048 fp16 (2x Chebyshev folded)
__device__ __half g_xThi[BB*(size_t)FT*NN];// x^T fp16

// ------------------------------ helpers ------------------------------
__device__ __forceinline__ u32 smem_u32(const void* p) {
    u32 a;
    asm("{ .reg .u64 t; cvta.to.shared.u64 t, %1; cvt.u32.u64 %0, t; }" : "=r"(a) : "l"(p));
    return a;
}
__device__ __forceinline__ void cp16(u32 dst, const void* src) {
    asm volatile("cp.async.cg.shared.global [%0], [%1], 16;" :: "r"(dst), "l"(src));
}
#define CP_COMMIT() asm volatile("cp.async.commit_group;" ::: "memory")
#define CP_WAIT(n)  asm volatile("cp.async.wait_group %0;" :: "n"(n) : "memory")

__device__ __forceinline__ void ldsm_x4(u32* r, u32 addr) {
    asm volatile("ldmatrix.sync.aligned.m8n8.x4.shared.b16 {%0,%1,%2,%3}, [%4];"
        : "=r"(r[0]), "=r"(r[1]), "=r"(r[2]), "=r"(r[3]) : "r"(addr));
}
__device__ __forceinline__ void ldsm_x2(u32* r, u32 addr) {
    asm volatile("ldmatrix.sync.aligned.m8n8.x2.shared.b16 {%0,%1}, [%2];"
        : "=r"(r[0]), "=r"(r[1]) : "r"(addr));
}
__device__ __forceinline__ void mma_f16(float* d, const u32* a, const u32* b) {
    asm volatile("mma.sync.aligned.m16n8k16.row.col.f32.f16.f16.f32 "
        "{%0,%1,%2,%3}, {%4,%5,%6,%7}, {%8,%9}, {%0,%1,%2,%3};"
        : "+f"(d[0]), "+f"(d[1]), "+f"(d[2]), "+f"(d[3])
        : "r"(a[0]), "r"(a[1]), "r"(a[2]), "r"(a[3]), "r"(b[0]), "r"(b[1]));
}

// ---------------------------------------------------------------------------
// Kernel 1: S = softmax(relu(E E^T), axis=1); 8 rows per block
// ---------------------------------------------------------------------------
__global__ __launch_bounds__(256)
void k_supports(const float* __restrict__ E) {
    extern __shared__ float sms[];
    float* rows = sms;              // 8*2048
    float* e8   = sms + 8*NN;       // 128
    float* pr   = e8 + 128;         // 8*256
    __shared__ float bc[8];

    const int i0  = blockIdx.x * 8;
    const int tid = threadIdx.x;
    const int w   = tid >> 5, lane = tid & 31;

    if (tid < 128) e8[tid] = E[(i0 + (tid >> 4))*FIN + (tid & 15)];
    __syncthreads();

    float lv[8];
    #pragma unroll
    for (int r = 0; r < 8; r++) lv[r] = 0.f;

    for (int j = tid; j < NN; j += 256) {
        float ej[16];
        const float4* p4 = reinterpret_cast<const float4*>(E + (size_t)j*FIN);
        #pragma unroll
        for (int q = 0; q < 4; q++) {
            float4 v = p4[q];
            ej[q*4+0] = v.x; ej[q*4+1] = v.y; ej[q*4+2] = v.z; ej[q*4+3] = v.w;
        }
        #pragma unroll
        for (int r = 0; r < 8; r++) {
            float dot = 0.f;
            #pragma unroll
            for (int q = 0; q < 16; q++) dot = fmaf(ej[q], e8[r*16+q], dot);
            float rv = fmaxf(dot, 0.f);
            rows[r*NN + j] = rv;
            lv[r] = fmaxf(lv[r], rv);
        }
    }
    #pragma unroll
    for (int r = 0; r < 8; r++) pr[r*256 + tid] = lv[r];
    __syncthreads();
    {
        float m = pr[w*256 + lane];
        #pragma unroll
        for (int o = 1; o < 8; o++) m = fmaxf(m, pr[w*256 + o*32 + lane]);
        #pragma unroll
        for (int o = 16; o > 0; o >>= 1) m = fmaxf(m, __shfl_xor_sync(0xffffffffu, m, o));
        if (lane == 0) bc[w] = m;
    }
    __syncthreads();
    float bmax[8];
    #pragma unroll
    for (int r = 0; r < 8; r++) { bmax[r] = bc[r]; lv[r] = 0.f; }
    __syncthreads();

    for (int j = tid; j < NN; j += 256)
        #pragma unroll
        for (int r = 0; r < 8; r++) {
            float e = expf(rows[r*NN + j] - bmax[r]);
            rows[r*NN + j] = e;
            lv[r] += e;
        }
    #pragma unroll
    for (int r = 0; r < 8; r++) pr[r*256 + tid] = lv[r];
    __syncthreads();
    {
        float s = pr[w*256 + lane];
        #pragma unroll
        for (int o = 1; o < 8; o++) s += pr[w*256 + o*32 + lane];
        #pragma unroll
        for (int o = 16; o > 0; o >>= 1) s += __shfl_xor_sync(0xffffffffu, s, o);
        if (lane == 0) bc[w] = 1.0f / s;
    }
    __syncthreads();
    float inv[8];
    #pragma unroll
    for (int r = 0; r < 8; r++) inv[r] = bc[r];

    for (int j = tid; j < NN; j += 256)
        #pragma unroll
        for (int r = 0; r < 8; r++) {
            float v = rows[r*NN + j] * inv[r];
            size_t o = (size_t)(i0 + r)*NN + j;
            g_S[o]   = v;
            g_Shi[o] = __float2half_rn(v * 1024.f);
        }
}

// ---------------------------------------------------------------------------
// Kernel 2: SThi (fp16 of S^T * 1024)
// ---------------------------------------------------------------------------
__global__ __launch_bounds__(256)
void k_prepS() {
    __shared__ float t[64][65];
    const int tid = threadIdx.x;
    const int i0 = blockIdx.y*64, j0 = blockIdx.x*64;

    for (int idx = tid; idx < 1024; idx += 256) {
        int r = idx >> 4, q = idx & 15;
        float4 v = *reinterpret_cast<const float4*>(&g_S[(size_t)(i0+r)*NN + j0 + q*4]);
        t[r][q*4+0] = v.x; t[r][q*4+1] = v.y; t[r][q*4+2] = v.z; t[r][q*4+3] = v.w;
    }
    __syncthreads();
    for (int idx = tid; idx < 4096; idx += 256) {
        int c = idx >> 6, r = idx & 63;
        g_SThi[(size_t)(j0+c)*NN + i0 + r] = __float2half_rn(t[r][c] * 1024.f);
    }
}

// ---------------------------------------------------------------------------
// Kernel 3: xT[b][ft][n] fp16
// ---------------------------------------------------------------------------
__global__ __launch_bounds__(256)
void k_prepx(const float* __restrict__ x) {
    __shared__ float t[FT][33];
    const int tid = threadIdx.x;
    const int b  = blockIdx.y;
    const int n0 = blockIdx.x*32;
    const float* xb = x + (size_t)b*NN*FT;

    for (int idx = tid; idx < 32*48; idx += 256) {
        int r = idx / 48, q = idx % 48;
        float4 v = *reinterpret_cast<const float4*>(&xb[(size_t)(n0+r)*FT + q*4]);
        t[q*4+0][r] = v.x; t[q*4+1][r] = v.y; t[q*4+2][r] = v.z; t[q*4+3][r] = v.w;
    }
    __syncthreads();
    for (int idx = tid; idx < FT*32; idx += 256) {
        int ft = idx >> 5, n = idx & 31;
        size_t o = ((size_t)b*FT + ft)*NN + n0 + n;
        g_xThi[o] = __float2half_rn(t[ft][n]);
    }
}

// ---------------------------------------------------------------------------
// Kernel 4: S2Th[i][j] = fp16( 2048 * sum_k ST[i,k]*S[j,k] )
// fp16 single-pass inputs scaled 2^20; output descale 2048/2^20 = 2^-9.
// CTA 128(i) x 256(j), 256 thr, 8 warps (2x4), warp tile 64x64, KC=64.
// ---------------------------------------------------------------------------
#define S2_BUFH (384*S2STR)     // halves per buffer
#define S2_BH   (128*S2STR)

__global__ __launch_bounds__(256, 1)
void k_s2() {
    extern __shared__ __align__(16) __half sh[];
    const int tid = threadIdx.x, w = tid >> 5, lane = tid & 31;
    const int wm = w >> 2, wn = w & 3;
    const int i0 = blockIdx.y*128, j0 = blockIdx.x*256;
    const u32 sb = smem_u32(sh);

    float d[4][8][4];
    #pragma unroll
    for (int mt = 0; mt < 4; mt++)
        #pragma unroll
        for (int nt = 0; nt < 8; nt++)
            #pragma unroll
            for (int e = 0; e < 4; e++) d[mt][nt][e] = 0.f;

    auto stage = [&](int ch) {
        const int n0 = ch*64;
        const u32 bufb = sb + (u32)((ch & 1) * S2_BUFH * 2);
        #pragma unroll
        for (int idx = tid; idx < 3072; idx += 256) {
            int ru = idx >> 3, q = idx & 7;
            const __half* src;
            int grow, dbase;
            if (ru < 128) { src = g_SThi; grow = i0 + ru;       dbase = 0; }
            else          { src = g_Shi;  grow = j0 + ru - 128; dbase = S2_BH; ru -= 128; }
            u32 dst = bufb + (u32)((dbase + ru*S2STR + q*8)*2);
            cp16(dst, src + (size_t)grow*NN + n0 + q*8);
        }
    };

    stage(0); CP_COMMIT();

    for (int ch = 0; ch < 32; ch++) {
        if (ch < 31) { stage(ch+1); CP_COMMIT(); CP_WAIT(1); }
        else         { CP_WAIT(0); }
        __syncthreads();

        const u32 bufb = sb + (u32)((ch & 1) * S2_BUFH * 2);
        #pragma unroll
        for (int ks = 0; ks < 4; ks++) {
            u32 ah[4][4], bh[8][2];
            const int arow = wm*64 + (lane & 15);
            const int acol = ks*16 + (lane >> 4)*8;
            const int brow = wn*64 + (lane & 7);
            const int bcol = ks*16 + ((lane >> 3) & 1)*8;
            #pragma unroll
            for (int nt = 0; nt < 8; nt++)
                ldsm_x2(bh[nt], bufb + (u32)(((S2_BH + (brow + nt*8)*S2STR) + bcol)*2));
            #pragma unroll
            for (int mt = 0; mt < 4; mt++)
                ldsm_x4(ah[mt], bufb + (u32)((((arow + mt*16)*S2STR) + acol)*2));
            #pragma unroll
            for (int mt = 0; mt < 4; mt++)
                #pragma unroll
                for (int nt = 0; nt < 8; nt++)
                    mma_f16(d[mt][nt], ah[mt], bh[nt]);
        }
        __syncthreads();
    }
    const float sc = 1.f / 512.f;   // 2048 / 2^20
    #pragma unroll
    for (int mt = 0; mt < 4; mt++)
        #pragma unroll
        for (int nt = 0; nt < 8; nt++) {
            int row = i0 + wm*64 + mt*16 + (lane >> 2);
            int col = j0 + wn*64 + nt*8 + (lane & 3)*2;
            *reinterpret_cast<__half2*>(&g_S2Th[(size_t)row*NN + col]) =
                __halves2half2(__float2half_rn(d[mt][nt][0]*sc), __float2half_rn(d[mt][nt][1]*sc));
            *reinterpret_cast<__half2*>(&g_S2Th[(size_t)(row+8)*NN + col]) =
                __halves2half2(__float2half_rn(d[mt][nt][2]*sc), __float2half_rn(d[mt][nt][3]*sc));
        }
}

// ---------------------------------------------------------------------------
// Kernel 5: masked dual-GEMM + FUSED theta epilogue + relu
//   W rows 0-63 : W1 = SThi*A (has 1024 scale) ; rows 64-127: W2 = S2Th*A (2048)
//   out[m,o,t] = relu(sum_f r1*th1 + r2*th2 + A[m,m]*x[m,ft]*(th0-th2))
// CTA: 256 thr, 2 CTAs/SM, M=128, N=192, KC=32, 8 warps (2x4), warp tile 64x48
// ---------------------------------------------------------------------------
#define KM_W(p)    ((p)*5120)                // halves: 128*40
#define KM_X(p)    (10240 + (p)*7680)        // halves: 192*40
#define KM_RAWB    51200                     // bytes
#define KM_STB     (KM_RAWB)                 // 64x32 halves = 4096 B
#define KM_S2B     (KM_RAWB + 4096)          // 64x32 halves = 4096 B
#define KM_AB      (KM_RAWB + 8192)          // 32x68 f32 = 8704 B
#define KM_SMEM    (KM_RAWB + 16896)         // 68096 B -> 2 CTAs/SM

__global__ __launch_bounds__(256, 2)
void k_main(const float* __restrict__ A, const float* __restrict__ x,
            const float* __restrict__ theta, float* __restrict__ out) {
    extern __shared__ __align__(16) __half sh[];
    char* shc = reinterpret_cast<char*>(sh);
    const int tid = threadIdx.x, w = tid >> 5, lane = tid & 31;
    const int wm = w >> 2, wn = w & 3;
    const int m0 = blockIdx.x*64;
    const int b  = blockIdx.y;
    const u32 sb = smem_u32(sh);

    const float* Ab = A + (size_t)b*NN*NN;
    const float* xb = x + (size_t)b*NN*FT;
    const __half* xh = g_xThi + (size_t)b*FT*NN;
    __half* sSTh = reinterpret_cast<__half*>(shc + KM_STB);
    __half* sS2h = reinterpret_cast<__half*>(shc + KM_S2B);
    float*  As   = reinterpret_cast<float*>(shc + KM_AB);

    float d[4][6][4];
    #pragma unroll
    for (int mt = 0; mt < 4; mt++)
        #pragma unroll
        for (int nt = 0; nt < 6; nt++)
            #pragma unroll
            for (int e = 0; e < 4; e++) d[mt][nt][e] = 0.f;

    auto stage = [&](int ch) {
        const int n0 = ch*32;
        const int p = ch & 1;
        #pragma unroll
        for (int idx = tid; idx < 1792; idx += 256) {
            if (idx < 768) {                 // X: 192 rows x 32 halves
                int row = idx >> 2, q = idx & 3;
                u32 dst = sb + (u32)((KM_X(p) + row*WSTR + q*8)*2);
                cp16(dst, xh + (size_t)row*NN + n0 + q*8);
            } else if (idx < 1280) {         // STh + S2h: 2 x 64 rows x 32 halves
                int j = idx - 768;
                int sel = j >> 8;            // 0: STh, 1: S2h
                int i = j & 255;
                int row = i >> 2, q = i & 3;
                const __half* src = sel ? g_S2Th : g_SThi;
                u32 dst = sb + (u32)((sel ? KM_S2B : KM_STB) + (row*32 + q*8)*2);
                cp16(dst, src + (size_t)(m0+row)*NN + n0 + q*8);
            } else {                         // raw A: 32 rows x 64 f32 (stride 68)
                int j = idx - 1280;
                int row = j >> 4, q = j & 15;
                u32 dst = sb + (u32)(KM_AB + (row*68 + q*4)*4);
                cp16(dst, Ab + (size_t)(n0+row)*NN + m0 + q*4);
            }
        }
    };

    auto build = [&](int ch) {
        const int p = ch & 1;
        #pragma unroll
        for (int idx = tid; idx < 1024; idx += 256) {
            int m = idx >> 4, pp = idx & 15, n = 2*pp;
            __half2 st = *reinterpret_cast<const __half2*>(&sSTh[m*32 + n]);
            __half2 s2 = *reinterpret_cast<const __half2*>(&sS2h[m*32 + n]);
            float a0 = As[n*68 + m], a1 = As[(n+1)*68 + m];
            __half h1x = __float2half_rn(__half2float(st.x)*a0);
            __half h1y = __float2half_rn(__half2float(st.y)*a1);
            __half h2x = __float2half_rn(__half2float(s2.x)*a0);
            __half h2y = __float2half_rn(__half2float(s2.y)*a1);
            int base = KM_W(p);
            *reinterpret_cast<__half2*>(shc + (base + m*WSTR + n)*2)      = __halves2half2(h1x, h1y);
            *reinterpret_cast<__half2*>(shc + (base + (64+m)*WSTR + n)*2) = __halves2half2(h2x, h2y);
        }
    };

    auto domma = [&](int ch) {
        const int p = ch & 1;
        const u32 wbase = sb + (u32)(KM_W(p)*2);
        const u32 xbase = sb + (u32)(KM_X(p)*2);
        #pragma unroll
        for (int ks = 0; ks < 2; ks++) {
            u32 ah[4][4], bh[6][2];
            const int arow = wm*64 + (lane & 15);
            const int acol = ks*16 + (lane >> 4)*8;
            const int brow = wn*48 + (lane & 7);
            const int bcol = ks*16 + ((lane >> 3) & 1)*8;
            #pragma unroll
            for (int nt = 0; nt < 6; nt++)
                ldsm_x2(bh[nt], xbase + (u32)(((brow + nt*8)*WSTR + bcol)*2));
            #pragma unroll
            for (int mt = 0; mt < 4; mt++)
                ldsm_x4(ah[mt], wbase + (u32)(((arow + mt*16)*WSTR + acol)*2));
            #pragma unroll
            for (int mt = 0; mt < 4; mt++)
                #pragma unroll
                for (int nt = 0; nt < 6; nt++)
                    mma_f16(d[mt][nt], ah[mt], bh[nt]);
        }
    };

    stage(0); CP_COMMIT();
    CP_WAIT(0); __syncthreads();
    build(0); __syncthreads();

    for (int c = 0; c < 64; c++) {
        if (c < 63) { stage(c+1); CP_COMMIT(); }
        domma(c);
        if (c < 63) {
            CP_WAIT(0); __syncthreads();
            build(c+1);
            __syncthreads();
        }
    }

    // ---------------- fused theta epilogue (fully unrolled mt) ----------------
    __syncthreads();   // all mma reads of pipeline smem done

    float* ep  = reinterpret_cast<float*>(shc);
    float* er1 = ep;            // 16*192 = 3072
    float* er2 = ep + 3072;     // 3072
    float* es0 = ep + 6144;     // 3072
    float* th1 = ep + 9216;     // 512
    float* th2 = ep + 9728;     // 512
    float* th0 = ep + 10240;    // 512  (theta0 - theta2)
    for (int i = tid; i < FIN*FOUT; i += 256) {
        th1[i] = theta[512 + i];
        float t2 = theta[1024 + i];
        th2[i]  = t2;
        th0[i]  = theta[i] - t2;
    }

    const float sc = 1.f / 1024.f;
    float* outb = out + (size_t)b*NN*FOUT*TT;

    #pragma unroll
    for (int mt = 0; mt < 4; mt++) {
        __syncthreads();   // previous quarter's reads done / theta visible
        {
            float* dst = (wm == 0) ? er1 : er2;
            int r16 = lane >> 2;
            int colb = wn*48 + (lane & 3)*2;
            #pragma unroll
            for (int nt = 0; nt < 6; nt++) {
                int col = colb + nt*8;
                dst[r16*FT + col]       = d[mt][nt][0]*sc;
                dst[r16*FT + col + 1]   = d[mt][nt][1]*sc;
                dst[(r16+8)*FT + col]   = d[mt][nt][2]*sc;
                dst[(r16+8)*FT + col+1] = d[mt][nt][3]*sc;
            }
        }
        for (int i = tid; i < 16*FT; i += 256) {
            int r = i / FT, c = i - r*FT;
            int mg = m0 + mt*16 + r;
            float dg = Ab[(size_t)mg*NN + mg];
            es0[i] = dg * xb[(size_t)mg*FT + c];
        }
        __syncthreads();
        for (int idx = tid; idx < 16*FOUT*TT; idx += 256) {
            int m = idx / (FOUT*TT);
            int r = idx - m*(FOUT*TT);
            int o = r / TT, t = r - o*TT;
            float val = 0.f;
            #pragma unroll
            for (int f = 0; f < FIN; f++) {
                int ft = f*TT + t;
                val = fmaf(er1[m*FT + ft], th1[f*FOUT + o], val);
                val = fmaf(er2[m*FT + ft], th2[f*FOUT + o], val);
                val = fmaf(es0[m*FT + ft], th0[f*FOUT + o], val);
            }
            outb[(size_t)(m0 + mt*16 + m)*FOUT*TT + r] = fmaxf(val, 0.f);
        }
    }
}

// ---------------------------------------------------------------------------
extern "C" void kernel_launch(void* const* d_in, const int* in_sizes, int n_in,
                              void* d_out, int out_size) {
    const float *x = nullptr, *A = nullptr, *E = nullptr, *theta = nullptr;
    for (int i = 0; i < n_in; i++) {
        switch (in_sizes[i]) {
            case BB*NN*FIN*TT:   x     = (const float*)d_in[i]; break;
            case BB*NN*NN:       A     = (const float*)d_in[i]; break;
            case NN*FIN:         E     = (const float*)d_in[i]; break;
            case 3*FIN*FOUT:     theta = (const float*)d_in[i]; break;
        }
    }
    float* out = (float*)d_out;

    const int sup_smem = (8*NN + 128 + 8*256) * (int)sizeof(float);
    cudaFuncSetAttribute(k_supports, cudaFuncAttributeMaxDynamicSharedMemorySize, sup_smem);
    k_supports<<<NN/8, 256, sup_smem>>>(E);

    k_prepS<<<dim3(32, 32), 256>>>();
    k_prepx<<<dim3(64, BB), 256>>>(x);

    const int s2_smem = 2 * S2_BUFH * 2;   // 110592 B
    cudaFuncSetAttribute(k_s2, cudaFuncAttributeMaxDynamicSharedMemorySize, s2_smem);
    k_s2<<<dim3(8, 16), 256, s2_smem>>>();

    cudaFuncSetAttribute(k_main, cudaFuncAttributeMaxDynamicSharedMemorySize, KM_SMEM);
    k_main<<<dim3(32, BB), 256, KM_SMEM>>>(A, x, theta, out);
}